// round 1
// baseline (speedup 1.0000x reference)
#include <cuda_runtime.h>

#define Q_TOTAL 65536
#define CPROT   64
#define DDIM    512
#define QT      128     // queries per block
#define KC      32      // K chunk staged in smem
#define QS_STRIDE 34    // padded row stride (floats) -> conflict-free LDS.64
#define PS_STRIDE 34

typedef unsigned long long u64;

// -------- device scratch (no allocations allowed) --------
__device__ float g_sump[2][CPROT];     // |proto|^2 per modality (0=rgb,1=flow)
__device__ float g_c  [2][Q_TOTAL];    // max posterior (confidence)
__device__ float g_h  [2][Q_TOTAL];    // entropy
__device__ float g_S  [2][Q_TOTAL];    // sum of e = exp(-dist)
__device__ float g_klfr[Q_TOTAL];      // (p_f*(log p_f - p_r)).mean
__device__ float g_klrf[Q_TOTAL];      // (p_r*(log p_r - p_f)).mean

__device__ __forceinline__ void ffma2(u64 &acc, u64 a, u64 b) {
    asm("fma.rn.f32x2 %0, %1, %2, %0;" : "+l"(acc) : "l"(a), "l"(b));
}
__device__ __forceinline__ float f2lo(u64 v) { return __uint_as_float((unsigned)(v & 0xffffffffu)); }
__device__ __forceinline__ float f2hi(u64 v) { return __uint_as_float((unsigned)(v >> 32)); }

// -------- kernel 1: per-proto squared norms --------
__global__ void sump_kernel(const float* __restrict__ ctx_r,
                            const float* __restrict__ ctx_f) {
    const float* ctx = (blockIdx.x == 0) ? ctx_r : ctx_f;
    int warp = threadIdx.x >> 5, lane = threadIdx.x & 31;
    for (int p = warp; p < CPROT; p += 8) {
        float s = 0.f;
        const float* row = ctx + (size_t)p * DDIM;
        for (int k = lane; k < DDIM; k += 32) { float v = row[k]; s += v * v; }
        #pragma unroll
        for (int o = 16; o; o >>= 1) s += __shfl_xor_sync(0xffffffffu, s, o);
        if (lane == 0) g_sump[blockIdx.x][p] = s;
    }
}

// -------- kernel 2: GEMM-ish posterior (dist -> e -> p, c, h, S) --------
__global__ void __launch_bounds__(256, 2)
posterior_kernel(const float* __restrict__ tgt_r, const float* __restrict__ tgt_f,
                 const float* __restrict__ ctx_r, const float* __restrict__ ctx_f,
                 float* __restrict__ out) {
    __shared__ float q_s[QT * QS_STRIDE];
    __shared__ float p_s[CPROT * PS_STRIDE];
    __shared__ float sumq_s[QT];

    const int mod = blockIdx.y;                 // 0=rgb, 1=flow
    const float* tgt = mod ? tgt_f : tgt_r;
    const float* ctx = mod ? ctx_f : ctx_r;
    // out layout: [0]=L_f_r, [1]=L_r_f, p_f @ 2, p_r @ 2+QC, post @ 2+2QC
    float* out_p = out + 2 + (mod ? (size_t)0 : (size_t)Q_TOTAL * CPROT);

    const int tid = threadIdx.x;
    const int qg  = tid >> 4;                   // 0..15: owns queries qg+16i
    const int pg  = tid & 15;                   // 0..15: owns protos  pg+16j
    const size_t qbase = (size_t)blockIdx.x * QT;

    u64 acc[8][4];
    #pragma unroll
    for (int i = 0; i < 8; ++i)
        #pragma unroll
        for (int j = 0; j < 4; ++j) acc[i][j] = 0ull;

    float accq2[4] = {0.f, 0.f, 0.f, 0.f};     // |q|^2 partials, free during staging

    for (int kc = 0; kc < DDIM; kc += KC) {
        __syncthreads();
        // stage queries: 128 x 32 floats = 1024 float4, 4 per thread
        #pragma unroll
        for (int i = 0; i < 4; ++i) {
            int f  = i * 256 + tid;
            int q  = f >> 3;
            int kf = f & 7;
            float4 v = *(const float4*)&tgt[(qbase + q) * DDIM + kc + kf * 4];
            float* dst = &q_s[q * QS_STRIDE + kf * 4];
            *(float2*)(dst)     = make_float2(v.x, v.y);
            *(float2*)(dst + 2) = make_float2(v.z, v.w);
            accq2[i] += v.x * v.x + v.y * v.y + v.z * v.z + v.w * v.w;
        }
        // stage protos: 64 x 32 floats = 512 float4, 2 per thread
        #pragma unroll
        for (int j = 0; j < 2; ++j) {
            int g  = j * 256 + tid;
            int p  = g >> 3;
            int kf = g & 7;
            float4 v = *(const float4*)&ctx[(size_t)p * DDIM + kc + kf * 4];
            float* dst = &p_s[p * PS_STRIDE + kf * 4];
            *(float2*)(dst)     = make_float2(v.x, v.y);
            *(float2*)(dst + 2) = make_float2(v.z, v.w);
        }
        __syncthreads();
        // FFMA2 mainloop: k-pairs accumulate into packed f32x2 partial sums
        #pragma unroll
        for (int k = 0; k < KC; k += 2) {
            u64 qv[8], pv[4];
            #pragma unroll
            for (int i = 0; i < 8; ++i)
                qv[i] = *(const u64*)&q_s[(qg + 16 * i) * QS_STRIDE + k];
            #pragma unroll
            for (int j = 0; j < 4; ++j)
                pv[j] = *(const u64*)&p_s[(pg + 16 * j) * PS_STRIDE + k];
            #pragma unroll
            for (int i = 0; i < 8; ++i)
                #pragma unroll
                for (int j = 0; j < 4; ++j)
                    ffma2(acc[i][j], qv[i], pv[j]);
        }
    }

    // reduce |q|^2 partials: 8 lanes (tid&7) share query q = 32*i + (tid>>3)
    #pragma unroll
    for (int i = 0; i < 4; ++i) {
        float s = accq2[i];
        s += __shfl_xor_sync(0xffffffffu, s, 1);
        s += __shfl_xor_sync(0xffffffffu, s, 2);
        s += __shfl_xor_sync(0xffffffffu, s, 4);
        if ((tid & 7) == 0) sumq_s[32 * i + (tid >> 3)] = s;
    }
    __syncthreads();

    float sump_reg[4];
    #pragma unroll
    for (int j = 0; j < 4; ++j) sump_reg[j] = g_sump[mod][pg + 16 * j];

    #pragma unroll
    for (int i = 0; i < 8; ++i) {
        int q = qg + 16 * i;
        float sq = sumq_s[q];
        float e[4], S = 0.f, T = 0.f, M = 0.f;
        #pragma unroll
        for (int j = 0; j < 4; ++j) {
            float dot  = f2lo(acc[i][j]) + f2hi(acc[i][j]);
            float d2   = sq - 2.f * dot + sump_reg[j];
            float dist = sqrtf(fmaxf(d2, 0.f));
            float ev   = expf(-dist);
            e[j] = ev;
            S += ev; T += ev * dist; M = fmaxf(M, ev);
        }
        // per-query reduce across the 16 pg lanes (aligned half-warp)
        #pragma unroll
        for (int o = 1; o < 16; o <<= 1) {
            S += __shfl_xor_sync(0xffffffffu, S, o);
            T += __shfl_xor_sync(0xffffffffu, T, o);
            M  = fmaxf(M, __shfl_xor_sync(0xffffffffu, M, o));
        }
        float invS = 1.0f / S;
        size_t qglob = qbase + q;
        #pragma unroll
        for (int j = 0; j < 4; ++j)
            out_p[qglob * CPROT + pg + 16 * j] = e[j] * invS;
        if (pg == 0) {
            g_c[mod][qglob] = M * invS;
            g_S[mod][qglob] = S;
            g_h[mod][qglob] = logf(S) + T * invS;   // == -sum p*log p
        }
    }
}

// -------- kernel 3: AMI fused posterior + per-query KL terms --------
__global__ void fuse_kernel(float* __restrict__ out) {
    int warp = threadIdx.x >> 5, lane = threadIdx.x & 31;
    size_t q = (size_t)blockIdx.x * 8 + warp;
    const float* p_f = out + 2;
    const float* p_r = out + 2 + (size_t)Q_TOTAL * CPROT;
    float* post      = out + 2 + 2 * (size_t)Q_TOTAL * CPROT;

    float2 pf = *(const float2*)&p_f[q * CPROT + 2 * lane];
    float2 pr = *(const float2*)&p_r[q * CPROT + 2 * lane];
    float cr = g_c[0][q], cf = g_c[1][q];
    float Sr = g_S[0][q], Sf = g_S[1][q];

    float klfr = pf.x * (logf(pf.x) - pr.x) + pf.y * (logf(pf.y) - pr.y);
    float klrf = pr.x * (logf(pr.x) - pf.x) + pr.y * (logf(pr.y) - pf.y);

    float inv = 1.f / (cr + cf);
    float a = cr * inv * Sr;     // w_r * S_r  -> reconstructs e_r = S_r * p_r
    float b = cf * inv * Sf;
    float fx = a * pr.x + b * pf.x;
    float fy = a * pr.y + b * pf.y;
    float fs = fx + fy;

    #pragma unroll
    for (int o = 1; o < 32; o <<= 1) {
        klfr += __shfl_xor_sync(0xffffffffu, klfr, o);
        klrf += __shfl_xor_sync(0xffffffffu, klrf, o);
        fs   += __shfl_xor_sync(0xffffffffu, fs, o);
    }
    float invfs = 1.f / fs;
    *(float2*)&post[q * CPROT + 2 * lane] = make_float2(fx * invfs, fy * invfs);
    if (lane == 0) {
        g_klfr[q] = klfr * (1.f / 64.f);
        g_klrf[q] = klrf * (1.f / 64.f);
    }
}

// -------- kernel 4: deterministic global reductions -> scalars --------
__global__ void final_kernel(float* __restrict__ out) {
    __shared__ float s_f[1024];
    __shared__ int   s_i[1024];
    int tid = threadIdx.x;

    int cnt = 0; float scr = 0.f, scf = 0.f;
    for (int i = tid; i < Q_TOTAL; i += 1024) {
        float hr = g_h[0][i], hf = g_h[1][i];
        float cr = g_c[0][i], cf = g_c[1][i];
        if (hr > hf && cr > cf) cnt++;
        scr += cr; scf += cf;
    }
    s_i[tid] = cnt; __syncthreads();
    for (int o = 512; o; o >>= 1) { if (tid < o) s_i[tid] += s_i[tid + o]; __syncthreads(); }
    int n_r = s_i[0];

    s_f[tid] = scr; __syncthreads();
    for (int o = 512; o; o >>= 1) { if (tid < o) s_f[tid] += s_f[tid + o]; __syncthreads(); }
    float sum_cr = s_f[0]; __syncthreads();

    s_f[tid] = scf; __syncthreads();
    for (int o = 512; o; o >>= 1) { if (tid < o) s_f[tid] += s_f[tid + o]; __syncthreads(); }
    float sum_cf = s_f[0]; __syncthreads();

    int n_f = Q_TOTAL - n_r;
    float sA = 0.f, sB = 0.f;
    for (int i = tid; i < Q_TOTAL; i += 1024) {
        if (i < n_f) sA += g_c[1][i] * g_klfr[i];
        if (i < n_r) sB += g_c[0][i] * g_klrf[i];
    }
    s_f[tid] = sA; __syncthreads();
    for (int o = 512; o; o >>= 1) { if (tid < o) s_f[tid] += s_f[tid + o]; __syncthreads(); }
    sA = s_f[0]; __syncthreads();

    s_f[tid] = sB; __syncthreads();
    for (int o = 512; o; o >>= 1) { if (tid < o) s_f[tid] += s_f[tid + o]; __syncthreads(); }
    if (tid == 0) {
        out[0] = sA / sum_cf;      // L_f_r
        out[1] = s_f[0] / sum_cr;  // L_r_f
    }
}

extern "C" void kernel_launch(void* const* d_in, const int* in_sizes, int n_in,
                              void* d_out, int out_size) {
    const float* ctx_r = (const float*)d_in[0];
    const float* ctx_f = (const float*)d_in[1];
    const float* tgt_r = (const float*)d_in[2];
    const float* tgt_f = (const float*)d_in[3];
    float* out = (float*)d_out;

    sump_kernel<<<2, 256>>>(ctx_r, ctx_f);
    posterior_kernel<<<dim3(Q_TOTAL / QT, 2), 256>>>(tgt_r, tgt_f, ctx_r, ctx_f, out);
    fuse_kernel<<<Q_TOTAL / 8, 256>>>(out);
    final_kernel<<<1, 1024>>>(out);
}

// round 3
// speedup vs baseline: 1.6817x; 1.6817x over previous
#include <cuda_runtime.h>
#include <cuda_bf16.h>
#include <cstdint>

#define Q_TOTAL 65536
#define CPROT   64
#define DDIM    512
#define QT      128
#define KC      64                  // floats per K chunk
#define NCH     (DDIM / KC)         // 8
#define AST     144                 // bytes per smem row (72 bf16, padded)

// ---- dynamic smem layout (bytes) ----
#define OFF_AHI  0
#define OFF_ALO  (OFF_AHI + QT * AST)       // 18432
#define OFF_BHI  (OFF_ALO + QT * AST)       // 36864
#define OFF_BLO  (OFF_BHI + CPROT * AST)    // 46080
#define OFF_SUMQ (OFF_BLO + CPROT * AST)    // 55296
#define OFF_SUMP (OFF_SUMQ + QT * 4)        // 55808
#define SMEM_TOTAL (OFF_SUMP + CPROT * 4)   // 56064

// -------- device scratch --------
__device__ float g_sump[2][CPROT];
__device__ float g_c  [2][Q_TOTAL];
__device__ float g_h  [2][Q_TOTAL];
__device__ float g_S  [2][Q_TOTAL];
__device__ float g_klfr[Q_TOTAL];
__device__ float g_klrf[Q_TOTAL];
__device__ float g_part[5][64];

// -------- helpers --------
__device__ __forceinline__ uint32_t smem_u32(const void* p) {
    uint32_t a;
    asm("{ .reg .u64 t; cvta.to.shared.u64 t, %1; cvt.u32.u64 %0, t; }"
        : "=r"(a) : "l"(p));
    return a;
}

#define LDM4(r, a) \
    asm volatile("ldmatrix.sync.aligned.m8n8.x4.shared.b16 {%0,%1,%2,%3}, [%4];" \
        : "=r"((r)[0]), "=r"((r)[1]), "=r"((r)[2]), "=r"((r)[3]) : "r"(a))

__device__ __forceinline__ void mma16816(float* d, const uint32_t* a, const uint32_t* b) {
    asm volatile(
        "mma.sync.aligned.m16n8k16.row.col.f32.bf16.bf16.f32 "
        "{%0,%1,%2,%3}, {%4,%5,%6,%7}, {%8,%9}, {%0,%1,%2,%3};"
        : "+f"(d[0]), "+f"(d[1]), "+f"(d[2]), "+f"(d[3])
        : "r"(a[0]), "r"(a[1]), "r"(a[2]), "r"(a[3]), "r"(b[0]), "r"(b[1]));
}

// pack 2 floats -> bf16x2 hi word, and produce lo residuals
__device__ __forceinline__ void split2(float x, float y, uint32_t& hi, uint32_t& lo) {
    __nv_bfloat162 h2 = __float22bfloat162_rn(make_float2(x, y));
    hi = *reinterpret_cast<uint32_t*>(&h2);
    float lx = x - __low2float(h2);
    float ly = y - __high2float(h2);
    __nv_bfloat162 l2 = __float22bfloat162_rn(make_float2(lx, ly));
    lo = *reinterpret_cast<uint32_t*>(&l2);
}

// -------- kernel 1: per-proto squared norms --------
__global__ void sump_kernel(const float* __restrict__ ctx_r,
                            const float* __restrict__ ctx_f) {
    const float* ctx = (blockIdx.x == 0) ? ctx_r : ctx_f;
    int warp = threadIdx.x >> 5, lane = threadIdx.x & 31;
    for (int p = warp; p < CPROT; p += 8) {
        float s = 0.f;
        const float* row = ctx + (size_t)p * DDIM;
        for (int k = lane; k < DDIM; k += 32) { float v = row[k]; s += v * v; }
        #pragma unroll
        for (int o = 16; o; o >>= 1) s += __shfl_xor_sync(0xffffffffu, s, o);
        if (lane == 0) g_sump[blockIdx.x][p] = s;
    }
}

// -------- kernel 2: mma.sync 3xBF16 posterior --------
extern __shared__ char sm_dyn[];

__global__ void __launch_bounds__(128, 2)
posterior_mma(const float* __restrict__ tgt_r, const float* __restrict__ tgt_f,
              const float* __restrict__ ctx_r, const float* __restrict__ ctx_f,
              float* __restrict__ out) {
    const int mod = blockIdx.y;
    const float* __restrict__ tgt = mod ? tgt_f : tgt_r;
    const float* __restrict__ ctx = mod ? ctx_f : ctx_r;
    float* out_p = out + 2 + (mod ? (size_t)0 : (size_t)Q_TOTAL * CPROT);

    const int tid = threadIdx.x;
    const int l   = tid & 31;
    const int w   = tid >> 5;
    const size_t qbase = (size_t)blockIdx.x * QT;

    char* sm = sm_dyn;
    const uint32_t sb = smem_u32(sm);
    float* sumq = (float*)(sm + OFF_SUMQ);
    float* sump = (float*)(sm + OFF_SUMP);

    if (tid < QT)    sumq[tid] = 0.f;
    if (tid < CPROT) sump[tid] = g_sump[mod][tid];

    float d[2][8][4];
    #pragma unroll
    for (int mt = 0; mt < 2; ++mt)
        #pragma unroll
        for (int nt = 0; nt < 8; ++nt)
            #pragma unroll
            for (int u = 0; u < 4; ++u) d[mt][nt][u] = 0.f;

    // ldmatrix lane offsets
    const uint32_t aoff = (uint32_t)((l & 15) * AST + (l >> 4) * 16);
    const uint32_t boff = (uint32_t)((((l & 7) + ((l >> 4) << 3))) * AST + (((l >> 3) & 1) * 16));
    const uint32_t aHi = sb + OFF_AHI + (w * 32) * AST + aoff;
    const uint32_t aLo = sb + OFF_ALO + (w * 32) * AST + aoff;
    const uint32_t bHi = sb + OFF_BHI + boff;
    const uint32_t bLo = sb + OFF_BLO + boff;

    for (int c = 0; c < NCH; ++c) {
        __syncthreads();               // smem consumed by previous chunk's ldmatrix
        const int kc = c * KC;

        // ---- stage A: 128 rows x 64 k, 16 float4 per thread ----
        #pragma unroll
        for (int i = 0; i < 16; ++i) {
            const int f   = i * 128 + tid;
            const int row = f >> 4;
            const int kq  = f & 15;
            float4 v = __ldcs((const float4*)(tgt + (qbase + row) * DDIM + kc + kq * 4));
            uint32_t h0, l0, h1, l1;
            split2(v.x, v.y, h0, l0);
            split2(v.z, v.w, h1, l1);
            *(uint2*)(sm + OFF_AHI + row * AST + kq * 8) = make_uint2(h0, h1);
            *(uint2*)(sm + OFF_ALO + row * AST + kq * 8) = make_uint2(l0, l1);
            float s = v.x * v.x + v.y * v.y + v.z * v.z + v.w * v.w;
            s += __shfl_xor_sync(0xffffffffu, s, 1);
            s += __shfl_xor_sync(0xffffffffu, s, 2);
            s += __shfl_xor_sync(0xffffffffu, s, 4);
            s += __shfl_xor_sync(0xffffffffu, s, 8);
            if ((tid & 15) == 0) sumq[row] += s;
        }
        // ---- stage B: 64 rows x 64 k, 8 float4 per thread ----
        #pragma unroll
        for (int j = 0; j < 8; ++j) {
            const int g   = j * 128 + tid;
            const int row = g >> 4;
            const int kq  = g & 15;
            float4 v = *(const float4*)(ctx + (size_t)row * DDIM + kc + kq * 4);
            uint32_t h0, l0, h1, l1;
            split2(v.x, v.y, h0, l0);
            split2(v.z, v.w, h1, l1);
            *(uint2*)(sm + OFF_BHI + row * AST + kq * 8) = make_uint2(h0, h1);
            *(uint2*)(sm + OFF_BLO + row * AST + kq * 8) = make_uint2(l0, l1);
        }
        __syncthreads();

        // ---- compute: 4 k-steps of 16 ----
        #pragma unroll
        for (int ks = 0; ks < 4; ++ks) {
            const uint32_t ko = ks * 32;
            uint32_t ah[2][4], al[2][4], bh[4][4], bl[4][4];
            LDM4(ah[0], aHi + ko);
            LDM4(ah[1], aHi + 16 * AST + ko);
            LDM4(al[0], aLo + ko);
            LDM4(al[1], aLo + 16 * AST + ko);
            #pragma unroll
            for (int n = 0; n < 4; ++n) {
                LDM4(bh[n], bHi + n * 16 * AST + ko);
                LDM4(bl[n], bLo + n * 16 * AST + ko);
            }
            #pragma unroll
            for (int mt = 0; mt < 2; ++mt)
                #pragma unroll
                for (int n = 0; n < 4; ++n) {
                    mma16816(d[mt][2 * n],     ah[mt], &bh[n][0]);  // hi*hi
                    mma16816(d[mt][2 * n + 1], ah[mt], &bh[n][2]);
                    mma16816(d[mt][2 * n],     ah[mt], &bl[n][0]);  // hi*lo
                    mma16816(d[mt][2 * n + 1], ah[mt], &bl[n][2]);
                    mma16816(d[mt][2 * n],     al[mt], &bh[n][0]);  // lo*hi
                    mma16816(d[mt][2 * n + 1], al[mt], &bh[n][2]);
                }
        }
    }
    __syncthreads();    // sumq complete

    // ---- epilogue: softmax / confidence / entropy ----
    const int qr    = l >> 2;
    const int cbase = (l & 3) * 2;
    float sp0[8], sp1[8];
    #pragma unroll
    for (int nt = 0; nt < 8; ++nt) {
        sp0[nt] = sump[8 * nt + cbase];
        sp1[nt] = sump[8 * nt + cbase + 1];
    }

    #pragma unroll
    for (int mt = 0; mt < 2; ++mt)
        #pragma unroll
        for (int h = 0; h < 2; ++h) {
            const int r = 32 * w + 16 * mt + qr + 8 * h;
            const float sq = sumq[r];
            float e[16], S = 0.f, T = 0.f, emax = 0.f;
            #pragma unroll
            for (int nt = 0; nt < 8; ++nt) {
                float dot0 = d[mt][nt][2 * h];
                float dot1 = d[mt][nt][2 * h + 1];
                float dist0 = sqrtf(fmaxf(sq - 2.f * dot0 + sp0[nt], 0.f));
                float dist1 = sqrtf(fmaxf(sq - 2.f * dot1 + sp1[nt], 0.f));
                float e0 = __expf(-dist0), e1 = __expf(-dist1);
                e[2 * nt] = e0; e[2 * nt + 1] = e1;
                S += e0 + e1;
                T += e0 * dist0 + e1 * dist1;
                emax = fmaxf(emax, fmaxf(e0, e1));
            }
            // quad reduce (lanes sharing the row)
            #pragma unroll
            for (int o = 1; o < 4; o <<= 1) {
                S += __shfl_xor_sync(0xffffffffu, S, o);
                T += __shfl_xor_sync(0xffffffffu, T, o);
                emax = fmaxf(emax, __shfl_xor_sync(0xffffffffu, emax, o));
            }
            const float invS = 1.f / S;
            const size_t qg = qbase + r;
            float* orow = &out_p[qg * CPROT];
            #pragma unroll
            for (int nt = 0; nt < 8; ++nt)
                *(float2*)&orow[8 * nt + cbase] =
                    make_float2(e[2 * nt] * invS, e[2 * nt + 1] * invS);
            if ((l & 3) == 0) {
                g_c[mod][qg] = emax * invS;
                g_S[mod][qg] = S;
                g_h[mod][qg] = logf(S) + T * invS;
            }
        }
}

// -------- kernel 3: AMI fused posterior + per-query KL terms --------
__global__ void fuse_kernel(float* __restrict__ out) {
    int warp = threadIdx.x >> 5, lane = threadIdx.x & 31;
    size_t q = (size_t)blockIdx.x * 8 + warp;
    const float* p_f = out + 2;
    const float* p_r = out + 2 + (size_t)Q_TOTAL * CPROT;
    float* post      = out + 2 + 2 * (size_t)Q_TOTAL * CPROT;

    float2 pf = *(const float2*)&p_f[q * CPROT + 2 * lane];
    float2 pr = *(const float2*)&p_r[q * CPROT + 2 * lane];
    float cr = g_c[0][q], cf = g_c[1][q];
    float Sr = g_S[0][q], Sf = g_S[1][q];

    float klfr = pf.x * (logf(pf.x) - pr.x) + pf.y * (logf(pf.y) - pr.y);
    float klrf = pr.x * (logf(pr.x) - pf.x) + pr.y * (logf(pr.y) - pf.y);

    float inv = 1.f / (cr + cf);
    float a = cr * inv * Sr;     // w_r * S_r  -> e_r = S_r * p_r
    float b = cf * inv * Sf;
    float fx = a * pr.x + b * pf.x;
    float fy = a * pr.y + b * pf.y;
    float fs = fx + fy;

    #pragma unroll
    for (int o = 1; o < 32; o <<= 1) {
        klfr += __shfl_xor_sync(0xffffffffu, klfr, o);
        klrf += __shfl_xor_sync(0xffffffffu, klrf, o);
        fs   += __shfl_xor_sync(0xffffffffu, fs, o);
    }
    float invfs = 1.f / fs;
    *(float2*)&post[q * CPROT + 2 * lane] = make_float2(fx * invfs, fy * invfs);
    if (lane == 0) {
        g_klfr[q] = klfr * (1.f / 64.f);
        g_klrf[q] = klrf * (1.f / 64.f);
    }
}

// -------- kernel 4a: per-chunk partials --------
__global__ void part_kernel() {
    __shared__ float sf[4][256];
    __shared__ int   si[256];
    int b = blockIdx.x, t = threadIdx.x;
    int base = b * 1024;
    int cnt = 0; float scr = 0.f, scf = 0.f, sA = 0.f, sB = 0.f;
    #pragma unroll
    for (int k = 0; k < 4; ++k) {
        int i = base + t + 256 * k;
        float hr = g_h[0][i], hf = g_h[1][i];
        float cr = g_c[0][i], cf = g_c[1][i];
        if (hr > hf && cr > cf) cnt++;
        scr += cr; scf += cf;
        sA += cf * g_klfr[i];
        sB += cr * g_klrf[i];
    }
    si[t] = cnt; sf[0][t] = scr; sf[1][t] = scf; sf[2][t] = sA; sf[3][t] = sB;
    __syncthreads();
    for (int o = 128; o; o >>= 1) {
        if (t < o) {
            si[t] += si[t + o];
            sf[0][t] += sf[0][t + o]; sf[1][t] += sf[1][t + o];
            sf[2][t] += sf[2][t + o]; sf[3][t] += sf[3][t + o];
        }
        __syncthreads();
    }
    if (t == 0) {
        g_part[0][b] = (float)si[0];
        g_part[1][b] = sf[0][0];
        g_part[2][b] = sf[1][0];
        g_part[3][b] = sf[2][0];
        g_part[4][b] = sf[3][0];
    }
}

// -------- kernel 4b: finalize scalars --------
__global__ void finalize_kernel(float* __restrict__ out) {
    __shared__ float red[1024];
    __shared__ int sh_nf, sh_nr;
    __shared__ float sh_scr, sh_scf, sh_fa, sh_fb;
    int t = threadIdx.x;
    if (t == 0) {
        int cnt = 0; float scr = 0.f, scf = 0.f;
        for (int b = 0; b < 64; ++b) {
            cnt += (int)g_part[0][b]; scr += g_part[1][b]; scf += g_part[2][b];
        }
        int nr = cnt, nf = Q_TOTAL - cnt;
        float fa = 0.f, fb = 0.f;
        for (int b = 0; b < (nf >> 10); ++b) fa += g_part[3][b];
        for (int b = 0; b < (nr >> 10); ++b) fb += g_part[4][b];
        sh_nf = nf; sh_nr = nr; sh_scr = scr; sh_scf = scf; sh_fa = fa; sh_fb = fb;
    }
    __syncthreads();
    int nf = sh_nf, nr = sh_nr;

    int iA = ((nf >> 10) << 10) + t;
    float vA = 0.f;
    if (iA < nf) vA = g_c[1][iA] * g_klfr[iA];
    red[t] = vA; __syncthreads();
    for (int o = 512; o; o >>= 1) { if (t < o) red[t] += red[t + o]; __syncthreads(); }
    float remA = red[0]; __syncthreads();

    int iB = ((nr >> 10) << 10) + t;
    float vB = 0.f;
    if (iB < nr) vB = g_c[0][iB] * g_klrf[iB];
    red[t] = vB; __syncthreads();
    for (int o = 512; o; o >>= 1) { if (t < o) red[t] += red[t + o]; __syncthreads(); }

    if (t == 0) {
        out[0] = (sh_fa + remA)   / sh_scf;   // L_f_r
        out[1] = (sh_fb + red[0]) / sh_scr;   // L_r_f
    }
}

extern "C" void kernel_launch(void* const* d_in, const int* in_sizes, int n_in,
                              void* d_out, int out_size) {
    const float* ctx_r = (const float*)d_in[0];
    const float* ctx_f = (const float*)d_in[1];
    const float* tgt_r = (const float*)d_in[2];
    const float* tgt_f = (const float*)d_in[3];
    float* out = (float*)d_out;

    cudaFuncSetAttribute(posterior_mma, cudaFuncAttributeMaxDynamicSharedMemorySize,
                         SMEM_TOTAL);

    sump_kernel<<<2, 256>>>(ctx_r, ctx_f);
    posterior_mma<<<dim3(Q_TOTAL / QT, 2), 128, SMEM_TOTAL>>>(tgt_r, tgt_f,
                                                              ctx_r, ctx_f, out);
    fuse_kernel<<<Q_TOTAL / 8, 256>>>(out);
    part_kernel<<<64, 256>>>();
    finalize_kernel<<<1, 1024>>>(out);
}

// round 4
// speedup vs baseline: 2.0363x; 1.2108x over previous
#include <cuda_runtime.h>
#include <cuda_bf16.h>
#include <cstdint>

#define Q_TOTAL 65536
#define CPROT   64
#define DDIM    512
#define QT      128
#define KC      64                  // floats per K chunk
#define NCH     (DDIM / KC)         // 8
#define AST     144                 // bytes per smem row (72 bf16, padded)

// ---- dynamic smem layout (bytes) ----
#define OFF_AHI  0
#define OFF_ALO  (OFF_AHI + QT * AST)       // 18432
#define OFF_BHI  (OFF_ALO + QT * AST)       // 36864
#define OFF_BLO  (OFF_BHI + CPROT * AST)    // 46080
#define OFF_SUMQ (OFF_BLO + CPROT * AST)    // 55296
#define OFF_SUMP (OFF_SUMQ + QT * 4)        // 55808
#define SMEM_TOTAL (OFF_SUMP + CPROT * 4)   // 56064

#define NPART 256

// -------- device scratch --------
__device__ float g_sump[2][CPROT];
__device__ float g_c  [2][Q_TOTAL];
__device__ float g_h  [2][Q_TOTAL];
__device__ float g_S  [2][Q_TOTAL];
__device__ float g_klfr[Q_TOTAL];
__device__ float g_klrf[Q_TOTAL];
__device__ float g_part[5][NPART];

// -------- helpers --------
__device__ __forceinline__ uint32_t smem_u32(const void* p) {
    uint32_t a;
    asm("{ .reg .u64 t; cvta.to.shared.u64 t, %1; cvt.u32.u64 %0, t; }"
        : "=r"(a) : "l"(p));
    return a;
}

#define LDM4(r, a) \
    asm volatile("ldmatrix.sync.aligned.m8n8.x4.shared.b16 {%0,%1,%2,%3}, [%4];" \
        : "=r"((r)[0]), "=r"((r)[1]), "=r"((r)[2]), "=r"((r)[3]) : "r"(a))

__device__ __forceinline__ void mma16816(float* d, const uint32_t* a, const uint32_t* b) {
    asm volatile(
        "mma.sync.aligned.m16n8k16.row.col.f32.bf16.bf16.f32 "
        "{%0,%1,%2,%3}, {%4,%5,%6,%7}, {%8,%9}, {%0,%1,%2,%3};"
        : "+f"(d[0]), "+f"(d[1]), "+f"(d[2]), "+f"(d[3])
        : "r"(a[0]), "r"(a[1]), "r"(a[2]), "r"(a[3]), "r"(b[0]), "r"(b[1]));
}

// pack 2 floats -> bf16x2 hi word + bf16x2 lo residual word
__device__ __forceinline__ void split2(float x, float y, uint32_t& hi, uint32_t& lo) {
    __nv_bfloat162 h2 = __float22bfloat162_rn(make_float2(x, y));
    hi = *reinterpret_cast<uint32_t*>(&h2);
    float lx = x - __low2float(h2);
    float ly = y - __high2float(h2);
    __nv_bfloat162 l2 = __float22bfloat162_rn(make_float2(lx, ly));
    lo = *reinterpret_cast<uint32_t*>(&l2);
}

// -------- kernel 1: per-proto squared norms --------
__global__ void sump_kernel(const float* __restrict__ ctx_r,
                            const float* __restrict__ ctx_f) {
    const float* ctx = (blockIdx.x == 0) ? ctx_r : ctx_f;
    int warp = threadIdx.x >> 5, lane = threadIdx.x & 31;
    for (int p = warp; p < CPROT; p += 8) {
        float s = 0.f;
        const float* row = ctx + (size_t)p * DDIM;
        for (int k = lane; k < DDIM; k += 32) { float v = row[k]; s += v * v; }
        #pragma unroll
        for (int o = 16; o; o >>= 1) s += __shfl_xor_sync(0xffffffffu, s, o);
        if (lane == 0) g_sump[blockIdx.x][p] = s;
    }
}

// -------- kernel 2: pipelined mma.sync 3xBF16 posterior --------
extern __shared__ char sm_dyn[];

__global__ void __launch_bounds__(256, 2)
posterior_mma(const float* __restrict__ tgt_r, const float* __restrict__ tgt_f,
              const float* __restrict__ ctx_r, const float* __restrict__ ctx_f,
              float* __restrict__ out) {
    const int mod = blockIdx.y;
    const float* __restrict__ tgt = mod ? tgt_f : tgt_r;
    const float* __restrict__ ctx = mod ? ctx_f : ctx_r;
    float* out_p = out + 2 + (mod ? (size_t)0 : (size_t)Q_TOTAL * CPROT);

    const int tid = threadIdx.x;
    const int l   = tid & 31;
    const int w   = tid >> 5;                 // 8 warps; warp owns q rows [16w,16w+16)
    const size_t qbase = (size_t)blockIdx.x * QT;

    char* sm = sm_dyn;
    const uint32_t sb = smem_u32(sm);
    float* sumq = (float*)(sm + OFF_SUMQ);
    float* sump = (float*)(sm + OFF_SUMP);

    if (tid < QT)    sumq[tid] = 0.f;
    if (tid < CPROT) sump[tid] = g_sump[mod][tid];

    float d[8][4];
    #pragma unroll
    for (int nt = 0; nt < 8; ++nt)
        #pragma unroll
        for (int u = 0; u < 4; ++u) d[nt][u] = 0.f;

    // ldmatrix lane offsets
    const uint32_t aoff = (uint32_t)((l & 15) * AST + (l >> 4) * 16);
    const uint32_t boff = (uint32_t)((((l & 7) + ((l >> 4) << 3))) * AST + (((l >> 3) & 1) * 16));
    const uint32_t aHi = sb + OFF_AHI + (w * 16) * AST + aoff;
    const uint32_t aLo = sb + OFF_ALO + (w * 16) * AST + aoff;
    const uint32_t bHi = sb + OFF_BHI + boff;
    const uint32_t bLo = sb + OFF_BLO + boff;

    // per-thread staging coordinates (A: 8 float4, B: 4 float4)
    const int arow = tid >> 4;                // base row tid>>4, +16 per i
    const int akq  = tid & 15;

    // ---- prologue: prefetch chunk 0 of A into registers ----
    float4 va[8];
    #pragma unroll
    for (int i = 0; i < 8; ++i)
        va[i] = __ldcs((const float4*)(tgt + (qbase + 16 * i + arow) * DDIM + akq * 4));

    for (int c = 0; c < NCH; ++c) {
        const int kc = c * KC;
        __syncthreads();                       // buffer free (prev chunk consumed)

        // ---- store A from regs (split bf16), accumulate |q|^2 ----
        #pragma unroll
        for (int i = 0; i < 8; ++i) {
            const int row = 16 * i + arow;
            uint32_t h0, l0, h1, l1;
            split2(va[i].x, va[i].y, h0, l0);
            split2(va[i].z, va[i].w, h1, l1);
            *(uint2*)(sm + OFF_AHI + row * AST + akq * 8) = make_uint2(h0, h1);
            *(uint2*)(sm + OFF_ALO + row * AST + akq * 8) = make_uint2(l0, l1);
            float s = va[i].x * va[i].x + va[i].y * va[i].y
                    + va[i].z * va[i].z + va[i].w * va[i].w;
            s += __shfl_xor_sync(0xffffffffu, s, 1);
            s += __shfl_xor_sync(0xffffffffu, s, 2);
            s += __shfl_xor_sync(0xffffffffu, s, 4);
            s += __shfl_xor_sync(0xffffffffu, s, 8);
            if ((tid & 15) == 0) sumq[row] += s;
        }
        // ---- B: load (L2-hot) + split + store ----
        #pragma unroll
        for (int j = 0; j < 4; ++j) {
            const int row = 16 * j + arow;
            float4 v = *(const float4*)(ctx + (size_t)row * DDIM + kc + akq * 4);
            uint32_t h0, l0, h1, l1;
            split2(v.x, v.y, h0, l0);
            split2(v.z, v.w, h1, l1);
            *(uint2*)(sm + OFF_BHI + row * AST + akq * 8) = make_uint2(h0, h1);
            *(uint2*)(sm + OFF_BLO + row * AST + akq * 8) = make_uint2(l0, l1);
        }
        __syncthreads();

        // ---- prefetch next chunk's A (latency hidden under MMAs below) ----
        if (c + 1 < NCH) {
            #pragma unroll
            for (int i = 0; i < 8; ++i)
                va[i] = __ldcs((const float4*)(tgt + (qbase + 16 * i + arow) * DDIM
                                               + kc + KC + akq * 4));
        }

        // ---- compute: 4 k-steps of 16 ----
        #pragma unroll
        for (int ks = 0; ks < 4; ++ks) {
            const uint32_t ko = ks * 32;
            uint32_t ah[4], al[4], bh[4][4], bl[4][4];
            LDM4(ah, aHi + ko);
            LDM4(al, aLo + ko);
            #pragma unroll
            for (int n = 0; n < 4; ++n) {
                LDM4(bh[n], bHi + n * 16 * AST + ko);
                LDM4(bl[n], bLo + n * 16 * AST + ko);
            }
            #pragma unroll
            for (int n = 0; n < 4; ++n) {
                mma16816(d[2 * n],     ah, &bh[n][0]);   // hi*hi
                mma16816(d[2 * n + 1], ah, &bh[n][2]);
                mma16816(d[2 * n],     ah, &bl[n][0]);   // hi*lo
                mma16816(d[2 * n + 1], ah, &bl[n][2]);
                mma16816(d[2 * n],     al, &bh[n][0]);   // lo*hi
                mma16816(d[2 * n + 1], al, &bh[n][2]);
            }
        }
    }
    __syncthreads();    // sumq complete

    // ---- epilogue: softmax / confidence / entropy ----
    const int qr    = l >> 2;
    const int cbase = (l & 3) * 2;
    float sp0[8], sp1[8];
    #pragma unroll
    for (int nt = 0; nt < 8; ++nt) {
        sp0[nt] = sump[8 * nt + cbase];
        sp1[nt] = sump[8 * nt + cbase + 1];
    }

    #pragma unroll
    for (int h = 0; h < 2; ++h) {
        const int r = 16 * w + qr + 8 * h;
        const float sq = sumq[r];
        float e[16], S = 0.f, T = 0.f, emax = 0.f;
        #pragma unroll
        for (int nt = 0; nt < 8; ++nt) {
            float dot0 = d[nt][2 * h];
            float dot1 = d[nt][2 * h + 1];
            float dist0 = sqrtf(fmaxf(sq - 2.f * dot0 + sp0[nt], 0.f));
            float dist1 = sqrtf(fmaxf(sq - 2.f * dot1 + sp1[nt], 0.f));
            float e0 = __expf(-dist0), e1 = __expf(-dist1);
            e[2 * nt] = e0; e[2 * nt + 1] = e1;
            S += e0 + e1;
            T += e0 * dist0 + e1 * dist1;
            emax = fmaxf(emax, fmaxf(e0, e1));
        }
        #pragma unroll
        for (int o = 1; o < 4; o <<= 1) {
            S += __shfl_xor_sync(0xffffffffu, S, o);
            T += __shfl_xor_sync(0xffffffffu, T, o);
            emax = fmaxf(emax, __shfl_xor_sync(0xffffffffu, emax, o));
        }
        const float invS = 1.f / S;
        const size_t qg = qbase + r;
        float* orow = &out_p[qg * CPROT];
        #pragma unroll
        for (int nt = 0; nt < 8; ++nt)
            *(float2*)&orow[8 * nt + cbase] =
                make_float2(e[2 * nt] * invS, e[2 * nt + 1] * invS);
        if ((l & 3) == 0) {
            g_c[mod][qg] = emax * invS;
            g_S[mod][qg] = S;
            g_h[mod][qg] = logf(S) + T * invS;
        }
    }
}

// -------- kernel 3: AMI fused posterior + per-query KL terms --------
__global__ void fuse_kernel(float* __restrict__ out) {
    int warp = threadIdx.x >> 5, lane = threadIdx.x & 31;
    size_t q = (size_t)blockIdx.x * 8 + warp;
    const float* p_f = out + 2;
    const float* p_r = out + 2 + (size_t)Q_TOTAL * CPROT;
    float* post      = out + 2 + 2 * (size_t)Q_TOTAL * CPROT;

    float2 pf = *(const float2*)&p_f[q * CPROT + 2 * lane];
    float2 pr = *(const float2*)&p_r[q * CPROT + 2 * lane];
    float cr = g_c[0][q], cf = g_c[1][q];
    float Sr = g_S[0][q], Sf = g_S[1][q];

    float klfr = pf.x * (logf(pf.x) - pr.x) + pf.y * (logf(pf.y) - pr.y);
    float klrf = pr.x * (logf(pr.x) - pf.x) + pr.y * (logf(pr.y) - pf.y);

    float inv = 1.f / (cr + cf);
    float a = cr * inv * Sr;     // w_r * S_r  -> e_r = S_r * p_r
    float b = cf * inv * Sf;
    float fx = a * pr.x + b * pf.x;
    float fy = a * pr.y + b * pf.y;
    float fs = fx + fy;

    #pragma unroll
    for (int o = 1; o < 32; o <<= 1) {
        klfr += __shfl_xor_sync(0xffffffffu, klfr, o);
        klrf += __shfl_xor_sync(0xffffffffu, klrf, o);
        fs   += __shfl_xor_sync(0xffffffffu, fs, o);
    }
    float invfs = 1.f / fs;
    *(float2*)&post[q * CPROT + 2 * lane] = make_float2(fx * invfs, fy * invfs);
    if (lane == 0) {
        g_klfr[q] = klfr * (1.f / 64.f);
        g_klrf[q] = klrf * (1.f / 64.f);
    }
}

// -------- kernel 4a: per-chunk partials (256 blocks x 256 elems) --------
__global__ void part_kernel() {
    __shared__ float sf[4][256];
    __shared__ int   si[256];
    int b = blockIdx.x, t = threadIdx.x;
    int i = b * 256 + t;
    float hr = g_h[0][i], hf = g_h[1][i];
    float cr = g_c[0][i], cf = g_c[1][i];
    si[t]    = (hr > hf && cr > cf) ? 1 : 0;
    sf[0][t] = cr;
    sf[1][t] = cf;
    sf[2][t] = cf * g_klfr[i];
    sf[3][t] = cr * g_klrf[i];
    __syncthreads();
    for (int o = 128; o; o >>= 1) {
        if (t < o) {
            si[t] += si[t + o];
            sf[0][t] += sf[0][t + o]; sf[1][t] += sf[1][t + o];
            sf[2][t] += sf[2][t + o]; sf[3][t] += sf[3][t + o];
        }
        __syncthreads();
    }
    if (t == 0) {
        g_part[0][b] = (float)si[0];
        g_part[1][b] = sf[0][0];
        g_part[2][b] = sf[1][0];
        g_part[3][b] = sf[2][0];
        g_part[4][b] = sf[3][0];
    }
}

// -------- kernel 4b: finalize scalars (all reductions parallel) --------
__global__ void finalize_kernel(float* __restrict__ out) {
    __shared__ float red[1024];
    __shared__ int   redi[1024];
    __shared__ int   sh_nf, sh_nr;
    __shared__ float sh_scr, sh_scf, sh_fa, sh_fb;
    int t = threadIdx.x;

    // phase 1: counts + confidence sums
    redi[t] = (t < NPART) ? (int)g_part[0][t] : 0;
    __syncthreads();
    for (int o = 512; o; o >>= 1) { if (t < o) redi[t] += redi[t + o]; __syncthreads(); }
    if (t == 0) { sh_nr = redi[0]; sh_nf = Q_TOTAL - redi[0]; }

    red[t] = (t < NPART) ? g_part[1][t] : 0.f;
    __syncthreads();
    for (int o = 512; o; o >>= 1) { if (t < o) red[t] += red[t + o]; __syncthreads(); }
    if (t == 0) sh_scr = red[0];
    __syncthreads();

    red[t] = (t < NPART) ? g_part[2][t] : 0.f;
    __syncthreads();
    for (int o = 512; o; o >>= 1) { if (t < o) red[t] += red[t + o]; __syncthreads(); }
    if (t == 0) sh_scf = red[0];
    __syncthreads();

    const int nf = sh_nf, nr = sh_nr;

    // phase 2: whole-chunk partial sums with cutoff
    red[t] = (t < NPART && t < (nf >> 8)) ? g_part[3][t] : 0.f;
    __syncthreads();
    for (int o = 512; o; o >>= 1) { if (t < o) red[t] += red[t + o]; __syncthreads(); }
    if (t == 0) sh_fa = red[0];
    __syncthreads();

    red[t] = (t < NPART && t < (nr >> 8)) ? g_part[4][t] : 0.f;
    __syncthreads();
    for (int o = 512; o; o >>= 1) { if (t < o) red[t] += red[t + o]; __syncthreads(); }
    if (t == 0) sh_fb = red[0];
    __syncthreads();

    // phase 3: remainder elements
    int iA = ((nf >> 8) << 8) + t;
    red[t] = (iA < nf) ? g_c[1][iA] * g_klfr[iA] : 0.f;
    __syncthreads();
    for (int o = 512; o; o >>= 1) { if (t < o) red[t] += red[t + o]; __syncthreads(); }
    float remA = red[0];
    __syncthreads();

    int iB = ((nr >> 8) << 8) + t;
    red[t] = (iB < nr) ? g_c[0][iB] * g_klrf[iB] : 0.f;
    __syncthreads();
    for (int o = 512; o; o >>= 1) { if (t < o) red[t] += red[t + o]; __syncthreads(); }

    if (t == 0) {
        out[0] = (sh_fa + remA)   / sh_scf;   // L_f_r
        out[1] = (sh_fb + red[0]) / sh_scr;   // L_r_f
    }
}

extern "C" void kernel_launch(void* const* d_in, const int* in_sizes, int n_in,
                              void* d_out, int out_size) {
    const float* ctx_r = (const float*)d_in[0];
    const float* ctx_f = (const float*)d_in[1];
    const float* tgt_r = (const float*)d_in[2];
    const float* tgt_f = (const float*)d_in[3];
    float* out = (float*)d_out;

    cudaFuncSetAttribute(posterior_mma, cudaFuncAttributeMaxDynamicSharedMemorySize,
                         SMEM_TOTAL);

    sump_kernel<<<2, 256>>>(ctx_r, ctx_f);
    posterior_mma<<<dim3(Q_TOTAL / QT, 2), 256, SMEM_TOTAL>>>(tgt_r, tgt_f,
                                                              ctx_r, ctx_f, out);
    fuse_kernel<<<Q_TOTAL / 8, 256>>>(out);
    part_kernel<<<NPART, 256>>>();
    finalize_kernel<<<1, 1024>>>(out);
}

// round 5
// speedup vs baseline: 2.2716x; 1.1156x over previous
#include <cuda_runtime.h>
#include <cuda_bf16.h>
#include <cstdint>

#define Q_TOTAL 65536
#define CPROT   64
#define DDIM    512
#define QT      128
#define KC      64                  // floats per K chunk
#define NCH     (DDIM / KC)         // 8
#define AST     144                 // bytes per smem row (72 bf16, padded)

// ---- dynamic smem layout (bytes) ----
#define OFF_AHI  0
#define OFF_ALO  (OFF_AHI + QT * AST)       // 18432
#define OFF_BHI  (OFF_ALO + QT * AST)       // 36864
#define OFF_BLO  (OFF_BHI + CPROT * AST)    // 46080
#define OFF_SUMQ (OFF_BLO + CPROT * AST)    // 55296 (128 floats)
#define OFF_SUMP (OFF_SUMQ + 512)           // 55808 (64 floats)
#define OFF_CMB  (OFF_SUMP + 256)           // 56064 (6*128 floats)
#define SMEM_TOTAL (OFF_CMB + 3072)         // 59136

#define NPART 8192

// -------- device scratch --------
__device__ float g_sump[2][CPROT];
__device__ uint4 g_bh4[2][4096];   // B hi split: [mod][row*64 + unit], 8 bf16/unit
__device__ uint4 g_bl4[2][4096];   // B lo split
__device__ float g_c  [2][Q_TOTAL];
__device__ float g_h  [2][Q_TOTAL];
__device__ float g_S  [2][Q_TOTAL];
__device__ float g_klfr[Q_TOTAL];
__device__ float g_klrf[Q_TOTAL];
__device__ float g_part[5][NPART];

// -------- helpers --------
__device__ __forceinline__ uint32_t smem_u32(const void* p) {
    uint32_t a;
    asm("{ .reg .u64 t; cvta.to.shared.u64 t, %1; cvt.u32.u64 %0, t; }"
        : "=r"(a) : "l"(p));
    return a;
}

#define LDM4(r, a) \
    asm volatile("ldmatrix.sync.aligned.m8n8.x4.shared.b16 {%0,%1,%2,%3}, [%4];" \
        : "=r"((r)[0]), "=r"((r)[1]), "=r"((r)[2]), "=r"((r)[3]) : "r"(a))

__device__ __forceinline__ void mma16816(float* d, const uint32_t* a, const uint32_t* b) {
    asm volatile(
        "mma.sync.aligned.m16n8k16.row.col.f32.bf16.bf16.f32 "
        "{%0,%1,%2,%3}, {%4,%5,%6,%7}, {%8,%9}, {%0,%1,%2,%3};"
        : "+f"(d[0]), "+f"(d[1]), "+f"(d[2]), "+f"(d[3])
        : "r"(a[0]), "r"(a[1]), "r"(a[2]), "r"(a[3]), "r"(b[0]), "r"(b[1]));
}

__device__ __forceinline__ void split2(float x, float y, uint32_t& hi, uint32_t& lo) {
    __nv_bfloat162 h2 = __float22bfloat162_rn(make_float2(x, y));
    hi = *reinterpret_cast<uint32_t*>(&h2);
    float lx = x - __low2float(h2);
    float ly = y - __high2float(h2);
    __nv_bfloat162 l2 = __float22bfloat162_rn(make_float2(lx, ly));
    lo = *reinterpret_cast<uint32_t*>(&l2);
}

// -------- kernel 1: proto norms + B bf16 split precompute --------
__global__ void prep_kernel(const float* __restrict__ ctx_r,
                            const float* __restrict__ ctx_f) {
    const int mod = blockIdx.x;
    const float* ctx = mod ? ctx_f : ctx_r;
    const int tid = threadIdx.x;
    const int warp = tid >> 5, lane = tid & 31;

    for (int p = warp; p < CPROT; p += 8) {
        float s = 0.f;
        const float* row = ctx + (size_t)p * DDIM;
        for (int k = lane; k < DDIM; k += 32) { float v = row[k]; s += v * v; }
        #pragma unroll
        for (int o = 16; o; o >>= 1) s += __shfl_xor_sync(0xffffffffu, s, o);
        if (lane == 0) g_sump[mod][p] = s;
    }
    // split: 4096 units of 8 floats
    for (int i = tid; i < 4096; i += 256) {
        const int row = i >> 6, u8 = i & 63;
        const float4 v0 = *(const float4*)(ctx + (size_t)row * DDIM + u8 * 8);
        const float4 v1 = *(const float4*)(ctx + (size_t)row * DDIM + u8 * 8 + 4);
        uint4 h, l;
        split2(v0.x, v0.y, h.x, l.x);
        split2(v0.z, v0.w, h.y, l.y);
        split2(v1.x, v1.y, h.z, l.z);
        split2(v1.z, v1.w, h.w, l.w);
        g_bh4[mod][i] = h;
        g_bl4[mod][i] = l;
    }
}

// -------- kernel 2: pipelined mma.sync 3xBF16 posterior --------
extern __shared__ char sm_dyn[];

__global__ void __launch_bounds__(256, 2)
posterior_mma(const float* __restrict__ tgt_r, const float* __restrict__ tgt_f,
              float* __restrict__ out) {
    const int mod = blockIdx.y;
    const float* __restrict__ tgt = mod ? tgt_f : tgt_r;
    float* out_p = out + 2 + (mod ? (size_t)0 : (size_t)Q_TOTAL * CPROT);

    const int tid = threadIdx.x;
    const int l   = tid & 31;
    const int w   = tid >> 5;
    const int wq  = w & 3;          // 4 q-groups of 32 rows
    const int wp  = w >> 2;         // 2 p-groups of 32 cols
    const size_t qbase = (size_t)blockIdx.x * QT;

    char* sm = sm_dyn;
    const uint32_t sb = smem_u32(sm);
    float* sumq = (float*)(sm + OFF_SUMQ);
    float* sump = (float*)(sm + OFF_SUMP);
    float* cmb  = (float*)(sm + OFF_CMB);

    if (tid < CPROT) sump[tid] = g_sump[mod][tid];

    float d[2][4][4];
    #pragma unroll
    for (int mt = 0; mt < 2; ++mt)
        #pragma unroll
        for (int n = 0; n < 4; ++n)
            #pragma unroll
            for (int u = 0; u < 4; ++u) d[mt][n][u] = 0.f;

    float qn[8] = {0.f, 0.f, 0.f, 0.f, 0.f, 0.f, 0.f, 0.f};

    // ldmatrix lane offsets
    const uint32_t aoff = (uint32_t)((l & 15) * AST + (l >> 4) * 16);
    const uint32_t boff = (uint32_t)(((l & 7) + ((l >> 4) << 3)) * AST + (((l >> 3) & 1) * 16));
    uint32_t aHiB[2], aLoB[2], bHiB[2], bLoB[2];
    #pragma unroll
    for (int mt = 0; mt < 2; ++mt) {
        aHiB[mt] = sb + OFF_AHI + (32 * wq + 16 * mt) * AST + aoff;
        aLoB[mt] = sb + OFF_ALO + (32 * wq + 16 * mt) * AST + aoff;
    }
    #pragma unroll
    for (int np = 0; np < 2; ++np) {
        bHiB[np] = sb + OFF_BHI + (32 * wp + 16 * np) * AST + boff;
        bLoB[np] = sb + OFF_BLO + (32 * wp + 16 * np) * AST + boff;
    }

    // per-thread staging coordinates
    const int arow = tid >> 4;
    const int akq  = tid & 15;

    // prologue: prefetch chunk 0 of A
    float4 va[8];
    #pragma unroll
    for (int i = 0; i < 8; ++i)
        va[i] = __ldcs((const float4*)(tgt + (qbase + 16 * i + arow) * DDIM + akq * 4));

    for (int c = 0; c < NCH; ++c) {
        const int kc = c * KC;
        __syncthreads();

        // ---- store A from regs (split bf16), accumulate |q|^2 in regs ----
        #pragma unroll
        for (int i = 0; i < 8; ++i) {
            const int row = 16 * i + arow;
            uint32_t h0, l0, h1, l1;
            split2(va[i].x, va[i].y, h0, l0);
            split2(va[i].z, va[i].w, h1, l1);
            *(uint2*)(sm + OFF_AHI + row * AST + akq * 8) = make_uint2(h0, h1);
            *(uint2*)(sm + OFF_ALO + row * AST + akq * 8) = make_uint2(l0, l1);
            qn[i] += va[i].x * va[i].x + va[i].y * va[i].y
                   + va[i].z * va[i].z + va[i].w * va[i].w;
        }
        // ---- B: copy prepared split (L2-hot) ----
        #pragma unroll
        for (int j = 0; j < 2; ++j) {
            const int g   = j * 256 + tid;
            const int row = g >> 3;
            const int u8  = g & 7;
            const int idx = row * 64 + (kc >> 3) + u8;
            *(uint4*)(sm + OFF_BHI + row * AST + u8 * 16) = g_bh4[mod][idx];
            *(uint4*)(sm + OFF_BLO + row * AST + u8 * 16) = g_bl4[mod][idx];
        }
        __syncthreads();

        // ---- prefetch next chunk's A ----
        if (c + 1 < NCH) {
            #pragma unroll
            for (int i = 0; i < 8; ++i)
                va[i] = __ldcs((const float4*)(tgt + (qbase + 16 * i + arow) * DDIM
                                               + kc + KC + akq * 4));
        }

        // ---- compute: 4 k-steps of 16 ----
        #pragma unroll
        for (int ks = 0; ks < 4; ++ks) {
            const uint32_t ko = ks * 32;
            uint32_t ah[2][4], al[2][4], bh[2][4], bl[2][4];
            #pragma unroll
            for (int mt = 0; mt < 2; ++mt) {
                LDM4(ah[mt], aHiB[mt] + ko);
                LDM4(al[mt], aLoB[mt] + ko);
            }
            #pragma unroll
            for (int np = 0; np < 2; ++np) {
                LDM4(bh[np], bHiB[np] + ko);
                LDM4(bl[np], bLoB[np] + ko);
            }
            #pragma unroll
            for (int mt = 0; mt < 2; ++mt)
                #pragma unroll
                for (int n = 0; n < 4; ++n) {
                    const int np = n >> 1, fo = (n & 1) * 2;
                    mma16816(d[mt][n], ah[mt], &bh[np][fo]);   // hi*hi
                    mma16816(d[mt][n], ah[mt], &bl[np][fo]);   // hi*lo
                    mma16816(d[mt][n], al[mt], &bh[np][fo]);   // lo*hi
                }
        }
    }

    // ---- reduce |q|^2 (once) ----
    #pragma unroll
    for (int i = 0; i < 8; ++i) {
        float s = qn[i];
        s += __shfl_xor_sync(0xffffffffu, s, 1);
        s += __shfl_xor_sync(0xffffffffu, s, 2);
        s += __shfl_xor_sync(0xffffffffu, s, 4);
        s += __shfl_xor_sync(0xffffffffu, s, 8);
        if ((tid & 15) == 0) sumq[16 * i + arow] = s;
    }
    __syncthreads();

    // ---- epilogue ----
    const int qr    = l >> 2;
    const int cbase = (l & 3) * 2;
    float sp[4][2];
    #pragma unroll
    for (int n = 0; n < 4; ++n) {
        sp[n][0] = sump[32 * wp + 8 * n + cbase];
        sp[n][1] = sump[32 * wp + 8 * n + cbase + 1];
    }

    // pass 1: per-warp partials over this warp's 32 cols; e overwrites d
    #pragma unroll
    for (int mt = 0; mt < 2; ++mt)
        #pragma unroll
        for (int h = 0; h < 2; ++h) {
            const int r = 32 * wq + 16 * mt + 8 * h + qr;
            const float sq = sumq[r];
            float S = 0.f, T = 0.f, emax = 0.f;
            #pragma unroll
            for (int n = 0; n < 4; ++n) {
                float dist0 = sqrtf(fmaxf(sq - 2.f * d[mt][n][2 * h]     + sp[n][0], 0.f));
                float dist1 = sqrtf(fmaxf(sq - 2.f * d[mt][n][2 * h + 1] + sp[n][1], 0.f));
                float e0 = __expf(-dist0), e1 = __expf(-dist1);
                d[mt][n][2 * h]     = e0;
                d[mt][n][2 * h + 1] = e1;
                S += e0 + e1;
                T += e0 * dist0 + e1 * dist1;
                emax = fmaxf(emax, fmaxf(e0, e1));
            }
            #pragma unroll
            for (int o = 1; o < 4; o <<= 1) {
                S += __shfl_xor_sync(0xffffffffu, S, o);
                T += __shfl_xor_sync(0xffffffffu, T, o);
                emax = fmaxf(emax, __shfl_xor_sync(0xffffffffu, emax, o));
            }
            if ((l & 3) == 0) {
                cmb[wp * 128 + r]       = S;
                cmb[256 + wp * 128 + r] = T;
                cmb[512 + wp * 128 + r] = emax;
            }
        }
    __syncthreads();

    // pass 2: combine across the two col-warps, write outputs
    #pragma unroll
    for (int mt = 0; mt < 2; ++mt)
        #pragma unroll
        for (int h = 0; h < 2; ++h) {
            const int r = 32 * wq + 16 * mt + 8 * h + qr;
            const float S = cmb[r] + cmb[128 + r];
            const float T = cmb[256 + r] + cmb[384 + r];
            const float M = fmaxf(cmb[512 + r], cmb[640 + r]);
            const float invS = 1.f / S;
            const size_t qg = qbase + r;
            float* orow = &out_p[qg * CPROT + 32 * wp];
            #pragma unroll
            for (int n = 0; n < 4; ++n)
                *(float2*)&orow[8 * n + cbase] =
                    make_float2(d[mt][n][2 * h] * invS, d[mt][n][2 * h + 1] * invS);
            if (wp == 0 && (l & 3) == 0) {
                g_c[mod][qg] = M * invS;
                g_S[mod][qg] = S;
                g_h[mod][qg] = logf(S) + T * invS;
            }
        }
}

// -------- kernel 3: AMI fuse + per-query KL + block partials --------
__global__ void fuse_kernel(float* __restrict__ out) {
    __shared__ float sm5[5][8];
    int warp = threadIdx.x >> 5, lane = threadIdx.x & 31;
    size_t q = (size_t)blockIdx.x * 8 + warp;
    const float* p_f = out + 2;
    const float* p_r = out + 2 + (size_t)Q_TOTAL * CPROT;
    float* post      = out + 2 + 2 * (size_t)Q_TOTAL * CPROT;

    float2 pf = *(const float2*)&p_f[q * CPROT + 2 * lane];
    float2 pr = *(const float2*)&p_r[q * CPROT + 2 * lane];
    float cr = g_c[0][q], cf = g_c[1][q];
    float Sr = g_S[0][q], Sf = g_S[1][q];
    float hr = g_h[0][q], hf = g_h[1][q];

    float klfr = pf.x * (logf(pf.x) - pr.x) + pf.y * (logf(pf.y) - pr.y);
    float klrf = pr.x * (logf(pr.x) - pf.x) + pr.y * (logf(pr.y) - pf.y);

    float inv = 1.f / (cr + cf);
    float a = cr * inv * Sr;
    float b = cf * inv * Sf;
    float fx = a * pr.x + b * pf.x;
    float fy = a * pr.y + b * pf.y;
    float fs = fx + fy;

    #pragma unroll
    for (int o = 1; o < 32; o <<= 1) {
        klfr += __shfl_xor_sync(0xffffffffu, klfr, o);
        klrf += __shfl_xor_sync(0xffffffffu, klrf, o);
        fs   += __shfl_xor_sync(0xffffffffu, fs, o);
    }
    float invfs = 1.f / fs;
    *(float2*)&post[q * CPROT + 2 * lane] = make_float2(fx * invfs, fy * invfs);
    if (lane == 0) {
        float kf = klfr * (1.f / 64.f);
        float kr = klrf * (1.f / 64.f);
        g_klfr[q] = kf;
        g_klrf[q] = kr;
        sm5[0][warp] = (hr > hf && cr > cf) ? 1.f : 0.f;
        sm5[1][warp] = cr;
        sm5[2][warp] = cf;
        sm5[3][warp] = cf * kf;
        sm5[4][warp] = cr * kr;
    }
    __syncthreads();
    if (threadIdx.x < 5) {
        float s = 0.f;
        #pragma unroll
        for (int k = 0; k < 8; ++k) s += sm5[threadIdx.x][k];
        g_part[threadIdx.x][blockIdx.x] = s;
    }
}

// -------- kernel 4: finalize scalars --------
__global__ void finalize_kernel(float* __restrict__ out) {
    __shared__ float red[1024];
    __shared__ int   sh_nf, sh_nr;
    __shared__ float sh_scr, sh_scf, sh_fa, sh_fb;
    const int t = threadIdx.x;

    // phase 1: count + confidence sums (each thread sums 8 contiguous partials)
    {
        float s = 0.f;
        #pragma unroll
        for (int k = 0; k < 8; ++k) s += g_part[0][t * 8 + k];
        red[t] = s; __syncthreads();
        for (int o = 512; o; o >>= 1) { if (t < o) red[t] += red[t + o]; __syncthreads(); }
        if (t == 0) { sh_nr = (int)red[0]; sh_nf = Q_TOTAL - (int)red[0]; }
        __syncthreads();

        s = 0.f;
        #pragma unroll
        for (int k = 0; k < 8; ++k) s += g_part[1][t * 8 + k];
        red[t] = s; __syncthreads();
        for (int o = 512; o; o >>= 1) { if (t < o) red[t] += red[t + o]; __syncthreads(); }
        if (t == 0) sh_scr = red[0];
        __syncthreads();

        s = 0.f;
        #pragma unroll
        for (int k = 0; k < 8; ++k) s += g_part[2][t * 8 + k];
        red[t] = s; __syncthreads();
        for (int o = 512; o; o >>= 1) { if (t < o) red[t] += red[t + o]; __syncthreads(); }
        if (t == 0) sh_scf = red[0];
        __syncthreads();
    }
    const int nf = sh_nf, nr = sh_nr;
    const int fbA = nf >> 3, fbB = nr >> 3;   // fully-included fuse blocks

    // phase 2: masked full-block sums
    {
        float s = 0.f;
        #pragma unroll
        for (int k = 0; k < 8; ++k) {
            int b = t * 8 + k;
            if (b < fbA) s += g_part[3][b];
        }
        red[t] = s; __syncthreads();
        for (int o = 512; o; o >>= 1) { if (t < o) red[t] += red[t + o]; __syncthreads(); }
        if (t == 0) sh_fa = red[0];
        __syncthreads();

        s = 0.f;
        #pragma unroll
        for (int k = 0; k < 8; ++k) {
            int b = t * 8 + k;
            if (b < fbB) s += g_part[4][b];
        }
        red[t] = s; __syncthreads();
        for (int o = 512; o; o >>= 1) { if (t < o) red[t] += red[t + o]; __syncthreads(); }
        if (t == 0) sh_fb = red[0];
        __syncthreads();
    }

    // phase 3: remainder elements (< 8 each)
    {
        int iA = fbA * 8 + t;
        red[t] = (t < 8 && iA < nf) ? g_c[1][iA] * g_klfr[iA] : 0.f;
        __syncthreads();
        for (int o = 512; o; o >>= 1) { if (t < o) red[t] += red[t + o]; __syncthreads(); }
        float remA = red[0];
        __syncthreads();

        int iB = fbB * 8 + t;
        red[t] = (t < 8 && iB < nr) ? g_c[0][iB] * g_klrf[iB] : 0.f;
        __syncthreads();
        for (int o = 512; o; o >>= 1) { if (t < o) red[t] += red[t + o]; __syncthreads(); }

        if (t == 0) {
            out[0] = (sh_fa + remA)   / sh_scf;   // L_f_r
            out[1] = (sh_fb + red[0]) / sh_scr;   // L_r_f
        }
    }
}

extern "C" void kernel_launch(void* const* d_in, const int* in_sizes, int n_in,
                              void* d_out, int out_size) {
    const float* ctx_r = (const float*)d_in[0];
    const float* ctx_f = (const float*)d_in[1];
    const float* tgt_r = (const float*)d_in[2];
    const float* tgt_f = (const float*)d_in[3];
    float* out = (float*)d_out;

    cudaFuncSetAttribute(posterior_mma, cudaFuncAttributeMaxDynamicSharedMemorySize,
                         SMEM_TOTAL);

    prep_kernel<<<2, 256>>>(ctx_r, ctx_f);
    posterior_mma<<<dim3(Q_TOTAL / QT, 2), 256, SMEM_TOTAL>>>(tgt_r, tgt_f, out);
    fuse_kernel<<<NPART, 256>>>(out);
    finalize_kernel<<<1, 1024>>>(out);
}

// round 6
// speedup vs baseline: 2.3738x; 1.0450x over previous
#include <cuda_runtime.h>
#include <cuda_bf16.h>
#include <cstdint>

#define Q_TOTAL 65536
#define CPROT   64
#define DDIM    512
#define QT      128
#define KC      64                  // floats per K chunk
#define NCH     (DDIM / KC)         // 8
#define AST     144                 // bytes per smem row (72 bf16, padded)

// ---- dynamic smem layout (bytes) ----
#define OFF_AHI  0
#define OFF_ALO  (OFF_AHI + QT * AST)       // 18432
#define OFF_BHI  (OFF_ALO + QT * AST)       // 36864
#define OFF_BLO  (OFF_BHI + CPROT * AST)    // 46080
#define OFF_SUMQ (OFF_BLO + CPROT * AST)    // 55296 (128 floats)
#define OFF_SUMP (OFF_SUMQ + 512)           // 55808 (64 floats)
#define OFF_CMB  (OFF_SUMP + 256)           // 56064 (6*128 floats)
#define SMEM_TOTAL (OFF_CMB + 3072)         // 59136

#define NPART 2048                          // fuse blocks (32 queries each)

// -------- device scratch --------
__device__ float g_sump[2][CPROT];
__device__ uint4 g_bh4[2][4096];   // B hi split: [mod][row*64 + unit], 8 bf16/unit
__device__ uint4 g_bl4[2][4096];   // B lo split
__device__ float g_c  [2][Q_TOTAL];
__device__ float g_h  [2][Q_TOTAL];
__device__ float g_S  [2][Q_TOTAL];
__device__ float g_klfr[Q_TOTAL];
__device__ float g_klrf[Q_TOTAL];
__device__ float g_part[5][NPART];

// -------- helpers --------
__device__ __forceinline__ uint32_t smem_u32(const void* p) {
    uint32_t a;
    asm("{ .reg .u64 t; cvta.to.shared.u64 t, %1; cvt.u32.u64 %0, t; }"
        : "=r"(a) : "l"(p));
    return a;
}

#define LDM4(r, a) \
    asm volatile("ldmatrix.sync.aligned.m8n8.x4.shared.b16 {%0,%1,%2,%3}, [%4];" \
        : "=r"((r)[0]), "=r"((r)[1]), "=r"((r)[2]), "=r"((r)[3]) : "r"(a))

__device__ __forceinline__ void mma16816(float* d, const uint32_t* a, const uint32_t* b) {
    asm volatile(
        "mma.sync.aligned.m16n8k16.row.col.f32.bf16.bf16.f32 "
        "{%0,%1,%2,%3}, {%4,%5,%6,%7}, {%8,%9}, {%0,%1,%2,%3};"
        : "+f"(d[0]), "+f"(d[1]), "+f"(d[2]), "+f"(d[3])
        : "r"(a[0]), "r"(a[1]), "r"(a[2]), "r"(a[3]), "r"(b[0]), "r"(b[1]));
}

__device__ __forceinline__ void split2(float x, float y, uint32_t& hi, uint32_t& lo) {
    __nv_bfloat162 h2 = __float22bfloat162_rn(make_float2(x, y));
    hi = *reinterpret_cast<uint32_t*>(&h2);
    float lx = x - __low2float(h2);
    float ly = y - __high2float(h2);
    __nv_bfloat162 l2 = __float22bfloat162_rn(make_float2(lx, ly));
    lo = *reinterpret_cast<uint32_t*>(&l2);
}

// -------- kernel 1: proto norms + B bf16 split precompute --------
__global__ void prep_kernel(const float* __restrict__ ctx_r,
                            const float* __restrict__ ctx_f) {
    const int mod = blockIdx.x;
    const float* ctx = mod ? ctx_f : ctx_r;
    const int tid = threadIdx.x;
    const int warp = tid >> 5, lane = tid & 31;

    for (int p = warp; p < CPROT; p += 8) {
        float s = 0.f;
        const float* row = ctx + (size_t)p * DDIM;
        for (int k = lane; k < DDIM; k += 32) { float v = row[k]; s += v * v; }
        #pragma unroll
        for (int o = 16; o; o >>= 1) s += __shfl_xor_sync(0xffffffffu, s, o);
        if (lane == 0) g_sump[mod][p] = s;
    }
    for (int i = tid; i < 4096; i += 256) {
        const int row = i >> 6, u8 = i & 63;
        const float4 v0 = *(const float4*)(ctx + (size_t)row * DDIM + u8 * 8);
        const float4 v1 = *(const float4*)(ctx + (size_t)row * DDIM + u8 * 8 + 4);
        uint4 h, l;
        split2(v0.x, v0.y, h.x, l.x);
        split2(v0.z, v0.w, h.y, l.y);
        split2(v1.x, v1.y, h.z, l.z);
        split2(v1.z, v1.w, h.w, l.w);
        g_bh4[mod][i] = h;
        g_bl4[mod][i] = l;
    }
}

// -------- kernel 2: pipelined mma.sync 3xBF16 posterior --------
extern __shared__ char sm_dyn[];

__global__ void __launch_bounds__(256, 2)
posterior_mma(const float* __restrict__ tgt_r, const float* __restrict__ tgt_f,
              float* __restrict__ out) {
    const int mod = blockIdx.y;
    const float* __restrict__ tgt = mod ? tgt_f : tgt_r;
    float* out_p = out + 2 + (mod ? (size_t)0 : (size_t)Q_TOTAL * CPROT);

    const int tid = threadIdx.x;
    const int l   = tid & 31;
    const int w   = tid >> 5;
    const int wq  = w & 3;
    const int wp  = w >> 2;
    const size_t qbase = (size_t)blockIdx.x * QT;

    char* sm = sm_dyn;
    const uint32_t sb = smem_u32(sm);
    float* sumq = (float*)(sm + OFF_SUMQ);
    float* sump = (float*)(sm + OFF_SUMP);
    float* cmb  = (float*)(sm + OFF_CMB);

    if (tid < CPROT) sump[tid] = g_sump[mod][tid];

    float d[2][4][4];
    #pragma unroll
    for (int mt = 0; mt < 2; ++mt)
        #pragma unroll
        for (int n = 0; n < 4; ++n)
            #pragma unroll
            for (int u = 0; u < 4; ++u) d[mt][n][u] = 0.f;

    float qn[8] = {0.f, 0.f, 0.f, 0.f, 0.f, 0.f, 0.f, 0.f};

    const uint32_t aoff = (uint32_t)((l & 15) * AST + (l >> 4) * 16);
    const uint32_t boff = (uint32_t)(((l & 7) + ((l >> 4) << 3)) * AST + (((l >> 3) & 1) * 16));
    uint32_t aHiB[2], aLoB[2], bHiB[2], bLoB[2];
    #pragma unroll
    for (int mt = 0; mt < 2; ++mt) {
        aHiB[mt] = sb + OFF_AHI + (32 * wq + 16 * mt) * AST + aoff;
        aLoB[mt] = sb + OFF_ALO + (32 * wq + 16 * mt) * AST + aoff;
    }
    #pragma unroll
    for (int np = 0; np < 2; ++np) {
        bHiB[np] = sb + OFF_BHI + (32 * wp + 16 * np) * AST + boff;
        bLoB[np] = sb + OFF_BLO + (32 * wp + 16 * np) * AST + boff;
    }

    const int arow = tid >> 4;
    const int akq  = tid & 15;

    float4 va[8];
    #pragma unroll
    for (int i = 0; i < 8; ++i)
        va[i] = __ldcs((const float4*)(tgt + (qbase + 16 * i + arow) * DDIM + akq * 4));

    for (int c = 0; c < NCH; ++c) {
        const int kc = c * KC;
        __syncthreads();

        #pragma unroll
        for (int i = 0; i < 8; ++i) {
            const int row = 16 * i + arow;
            uint32_t h0, l0, h1, l1;
            split2(va[i].x, va[i].y, h0, l0);
            split2(va[i].z, va[i].w, h1, l1);
            *(uint2*)(sm + OFF_AHI + row * AST + akq * 8) = make_uint2(h0, h1);
            *(uint2*)(sm + OFF_ALO + row * AST + akq * 8) = make_uint2(l0, l1);
            qn[i] += va[i].x * va[i].x + va[i].y * va[i].y
                   + va[i].z * va[i].z + va[i].w * va[i].w;
        }
        #pragma unroll
        for (int j = 0; j < 2; ++j) {
            const int g   = j * 256 + tid;
            const int row = g >> 3;
            const int u8  = g & 7;
            const int idx = row * 64 + (kc >> 3) + u8;
            *(uint4*)(sm + OFF_BHI + row * AST + u8 * 16) = g_bh4[mod][idx];
            *(uint4*)(sm + OFF_BLO + row * AST + u8 * 16) = g_bl4[mod][idx];
        }
        __syncthreads();

        if (c + 1 < NCH) {
            #pragma unroll
            for (int i = 0; i < 8; ++i)
                va[i] = __ldcs((const float4*)(tgt + (qbase + 16 * i + arow) * DDIM
                                               + kc + KC + akq * 4));
        }

        #pragma unroll
        for (int ks = 0; ks < 4; ++ks) {
            const uint32_t ko = ks * 32;
            uint32_t ah[2][4], al[2][4], bh[2][4], bl[2][4];
            #pragma unroll
            for (int mt = 0; mt < 2; ++mt) {
                LDM4(ah[mt], aHiB[mt] + ko);
                LDM4(al[mt], aLoB[mt] + ko);
            }
            #pragma unroll
            for (int np = 0; np < 2; ++np) {
                LDM4(bh[np], bHiB[np] + ko);
                LDM4(bl[np], bLoB[np] + ko);
            }
            #pragma unroll
            for (int mt = 0; mt < 2; ++mt)
                #pragma unroll
                for (int n = 0; n < 4; ++n) {
                    const int np = n >> 1, fo = (n & 1) * 2;
                    mma16816(d[mt][n], ah[mt], &bh[np][fo]);
                    mma16816(d[mt][n], ah[mt], &bl[np][fo]);
                    mma16816(d[mt][n], al[mt], &bh[np][fo]);
                }
        }
    }

    #pragma unroll
    for (int i = 0; i < 8; ++i) {
        float s = qn[i];
        s += __shfl_xor_sync(0xffffffffu, s, 1);
        s += __shfl_xor_sync(0xffffffffu, s, 2);
        s += __shfl_xor_sync(0xffffffffu, s, 4);
        s += __shfl_xor_sync(0xffffffffu, s, 8);
        if ((tid & 15) == 0) sumq[16 * i + arow] = s;
    }
    __syncthreads();

    const int qr    = l >> 2;
    const int cbase = (l & 3) * 2;
    float sp[4][2];
    #pragma unroll
    for (int n = 0; n < 4; ++n) {
        sp[n][0] = sump[32 * wp + 8 * n + cbase];
        sp[n][1] = sump[32 * wp + 8 * n + cbase + 1];
    }

    #pragma unroll
    for (int mt = 0; mt < 2; ++mt)
        #pragma unroll
        for (int h = 0; h < 2; ++h) {
            const int r = 32 * wq + 16 * mt + 8 * h + qr;
            const float sq = sumq[r];
            float S = 0.f, T = 0.f, emax = 0.f;
            #pragma unroll
            for (int n = 0; n < 4; ++n) {
                float dist0 = sqrtf(fmaxf(sq - 2.f * d[mt][n][2 * h]     + sp[n][0], 0.f));
                float dist1 = sqrtf(fmaxf(sq - 2.f * d[mt][n][2 * h + 1] + sp[n][1], 0.f));
                float e0 = __expf(-dist0), e1 = __expf(-dist1);
                d[mt][n][2 * h]     = e0;
                d[mt][n][2 * h + 1] = e1;
                S += e0 + e1;
                T += e0 * dist0 + e1 * dist1;
                emax = fmaxf(emax, fmaxf(e0, e1));
            }
            #pragma unroll
            for (int o = 1; o < 4; o <<= 1) {
                S += __shfl_xor_sync(0xffffffffu, S, o);
                T += __shfl_xor_sync(0xffffffffu, T, o);
                emax = fmaxf(emax, __shfl_xor_sync(0xffffffffu, emax, o));
            }
            if ((l & 3) == 0) {
                cmb[wp * 128 + r]       = S;
                cmb[256 + wp * 128 + r] = T;
                cmb[512 + wp * 128 + r] = emax;
            }
        }
    __syncthreads();

    #pragma unroll
    for (int mt = 0; mt < 2; ++mt)
        #pragma unroll
        for (int h = 0; h < 2; ++h) {
            const int r = 32 * wq + 16 * mt + 8 * h + qr;
            const float S = cmb[r] + cmb[128 + r];
            const float T = cmb[256 + r] + cmb[384 + r];
            const float M = fmaxf(cmb[512 + r], cmb[640 + r]);
            const float invS = 1.f / S;
            const size_t qg = qbase + r;
            float* orow = &out_p[qg * CPROT + 32 * wp];
            #pragma unroll
            for (int n = 0; n < 4; ++n)
                *(float2*)&orow[8 * n + cbase] =
                    make_float2(d[mt][n][2 * h] * invS, d[mt][n][2 * h + 1] * invS);
            if (wp == 0 && (l & 3) == 0) {
                g_c[mod][qg] = M * invS;
                g_S[mod][qg] = S;
                g_h[mod][qg] = logf(S) + T * invS;
            }
        }
}

// -------- kernel 3: AMI fuse + per-query KL + block partials (32 q/block) --------
__global__ void __launch_bounds__(1024)
fuse_kernel(float* __restrict__ out) {
    __shared__ float sm5[5][32];
    const int warp = threadIdx.x >> 5, lane = threadIdx.x & 31;
    const size_t q = (size_t)blockIdx.x * 32 + warp;
    const float* p_f = out + 2;
    const float* p_r = out + 2 + (size_t)Q_TOTAL * CPROT;
    float* post      = out + 2 + 2 * (size_t)Q_TOTAL * CPROT;

    float2 pf = *(const float2*)&p_f[q * CPROT + 2 * lane];
    float2 pr = *(const float2*)&p_r[q * CPROT + 2 * lane];
    float cr = g_c[0][q], cf = g_c[1][q];
    float Sr = g_S[0][q], Sf = g_S[1][q];
    float hr = g_h[0][q], hf = g_h[1][q];

    float klfr = pf.x * (logf(pf.x) - pr.x) + pf.y * (logf(pf.y) - pr.y);
    float klrf = pr.x * (logf(pr.x) - pf.x) + pr.y * (logf(pr.y) - pf.y);

    float inv = 1.f / (cr + cf);
    float a = cr * inv * Sr;
    float b = cf * inv * Sf;
    float fx = a * pr.x + b * pf.x;
    float fy = a * pr.y + b * pf.y;
    float fs = fx + fy;

    #pragma unroll
    for (int o = 1; o < 32; o <<= 1) {
        klfr += __shfl_xor_sync(0xffffffffu, klfr, o);
        klrf += __shfl_xor_sync(0xffffffffu, klrf, o);
        fs   += __shfl_xor_sync(0xffffffffu, fs, o);
    }
    float invfs = 1.f / fs;
    *(float2*)&post[q * CPROT + 2 * lane] = make_float2(fx * invfs, fy * invfs);
    if (lane == 0) {
        float kf = klfr * (1.f / 64.f);
        float kr = klrf * (1.f / 64.f);
        g_klfr[q] = kf;
        g_klrf[q] = kr;
        sm5[0][warp] = (hr > hf && cr > cf) ? 1.f : 0.f;
        sm5[1][warp] = cr;
        sm5[2][warp] = cf;
        sm5[3][warp] = cf * kf;
        sm5[4][warp] = cr * kr;
    }
    __syncthreads();
    if (threadIdx.x < 5) {
        float s = 0.f;
        #pragma unroll
        for (int k = 0; k < 32; ++k) s += sm5[threadIdx.x][k];
        g_part[threadIdx.x][blockIdx.x] = s;
    }
}

// -------- kernel 4: finalize scalars (2 trees total) --------
__global__ void __launch_bounds__(1024)
finalize_kernel(float* __restrict__ out) {
    __shared__ float r0[1024], r1[1024], r2[1024];
    __shared__ int   sh_nr;
    __shared__ float sh_scr, sh_scf;
    const int t = threadIdx.x;

    // phase 1: count + confidence sums, one combined tree
    r0[t] = g_part[0][2 * t] + g_part[0][2 * t + 1];
    r1[t] = g_part[1][2 * t] + g_part[1][2 * t + 1];
    r2[t] = g_part[2][2 * t] + g_part[2][2 * t + 1];
    __syncthreads();
    for (int o = 512; o; o >>= 1) {
        if (t < o) { r0[t] += r0[t + o]; r1[t] += r1[t + o]; r2[t] += r2[t + o]; }
        __syncthreads();
    }
    if (t == 0) { sh_nr = (int)r0[0]; sh_scr = r1[0]; sh_scf = r2[0]; }
    __syncthreads();

    const int nr = sh_nr, nf = Q_TOTAL - nr;
    const int fbA = nf >> 5, fbB = nr >> 5;   // fully-included 32-query blocks

    // phase 2: masked block sums + remainder elements, one combined tree
    const int b0 = 2 * t, b1 = 2 * t + 1;
    float sA = (b0 < fbA ? g_part[3][b0] : 0.f) + (b1 < fbA ? g_part[3][b1] : 0.f);
    float sB = (b0 < fbB ? g_part[4][b0] : 0.f) + (b1 < fbB ? g_part[4][b1] : 0.f);
    if (t < 32) {
        int iA = fbA * 32 + t;
        int iB = fbB * 32 + t;
        if (iA < nf) sA += g_c[1][iA] * g_klfr[iA];
        if (iB < nr) sB += g_c[0][iB] * g_klrf[iB];
    }
    r0[t] = sA; r1[t] = sB;
    __syncthreads();
    for (int o = 512; o; o >>= 1) {
        if (t < o) { r0[t] += r0[t + o]; r1[t] += r1[t + o]; }
        __syncthreads();
    }
    if (t == 0) {
        out[0] = r0[0] / sh_scf;   // L_f_r
        out[1] = r1[0] / sh_scr;   // L_r_f
    }
}

extern "C" void kernel_launch(void* const* d_in, const int* in_sizes, int n_in,
                              void* d_out, int out_size) {
    const float* ctx_r = (const float*)d_in[0];
    const float* ctx_f = (const float*)d_in[1];
    const float* tgt_r = (const float*)d_in[2];
    const float* tgt_f = (const float*)d_in[3];
    float* out = (float*)d_out;

    cudaFuncSetAttribute(posterior_mma, cudaFuncAttributeMaxDynamicSharedMemorySize,
                         SMEM_TOTAL);

    prep_kernel<<<2, 256>>>(ctx_r, ctx_f);
    posterior_mma<<<dim3(Q_TOTAL / QT, 2), 256, SMEM_TOTAL>>>(tgt_r, tgt_f, out);
    fuse_kernel<<<NPART, 1024>>>(out);
    finalize_kernel<<<1, 1024>>>(out);
}